// round 2
// baseline (speedup 1.0000x reference)
#include <cuda_runtime.h>
#include <cstdint>

#define NEURONS  4096
#define KSEL     512
#define NTHREADS 256
#define EPT      16          // elements per thread
#define VPT      4           // float4 loads per thread
#define NWARPS   (NTHREADS / 32)
#define SMALL_N  64          // switch to rank-select when candidates <= this

// ---- monotone float<->key transform (order-preserving for all finite floats) ----
__device__ __forceinline__ uint32_t f2key(uint32_t u) {
    return u ^ (uint32_t)(((int32_t)u >> 31) | 0x80000000u);
}
__device__ __forceinline__ float key2f(uint32_t k) {
    uint32_t m = (uint32_t)((int32_t)k >> 31);            // 0xFFFFFFFF if top bit set
    return __uint_as_float(k ^ (0x80000000u | ~m));
}

// Reduce 8 per-warp histograms, block suffix-scan (from bin 255 down), pick the
// bin where cumulative count crosses kk. Writes bin / residual-k / bin-count.
__device__ __forceinline__ void reduce_scan_select(
    uint32_t whist[NWARPS][256], uint32_t* warp_pref,
    uint32_t kk, uint32_t* sh_bin, uint32_t* sh_krem, uint32_t* sh_cnt,
    int tid, int lane, int wid)
{
    __syncthreads();                       // hist writes visible
    const int bin = 255 - tid;             // tid order == descending bins
    uint32_t h = 0;
    #pragma unroll
    for (int w = 0; w < NWARPS; w++) h += whist[w][bin];

    // inclusive scan over tid (== suffix sum over bins)
    uint32_t x = h;
    #pragma unroll
    for (int off = 1; off < 32; off <<= 1) {
        uint32_t y = __shfl_up_sync(0xFFFFFFFFu, x, off);
        if (lane >= off) x += y;
    }
    if (lane == 31) warp_pref[wid] = x;
    __syncthreads();
    if (wid == 0) {
        uint32_t t = (lane < NWARPS) ? warp_pref[lane] : 0u;
        #pragma unroll
        for (int off = 1; off < NWARPS; off <<= 1) {
            uint32_t y = __shfl_up_sync(0xFFFFFFFFu, t, off);
            if (lane >= off) t += y;
        }
        if (lane < NWARPS) warp_pref[lane] = t;
    }
    __syncthreads();
    uint32_t incl = x + (wid ? warp_pref[wid - 1] : 0u);
    uint32_t excl = incl - h;
    if (kk > excl && kk <= incl) {         // exactly one thread satisfies
        *sh_bin  = (uint32_t)bin;
        *sh_krem = kk - excl;
        *sh_cnt  = h;
    }
    __syncthreads();
}

__global__ void __launch_bounds__(NTHREADS, 4)
kwinners_kernel(const float* __restrict__ s, float* __restrict__ out)
{
    __shared__ uint32_t whist[NWARPS][256];   // per-warp private histograms (no atomics)
    __shared__ uint32_t warp_pref[NWARPS];
    __shared__ uint32_t cand[NEURONS];        // stage-1 candidate keys
    __shared__ uint32_t fcand[SMALL_N];       // final small candidate set
    __shared__ uint32_t sh_bin, sh_krem, sh_cnt, sh_ccnt, sh_fcnt, sh_T;

    const int tid  = threadIdx.x;
    const int lane = tid & 31;
    const int wid  = tid >> 5;
    const unsigned FULL = 0xFFFFFFFFu;
    const uint32_t lt_mask = (lane == 31) ? 0x7FFFFFFFu : ((1u << lane) - 1u);

    const size_t row = blockIdx.x;
    const float4* __restrict__ src = reinterpret_cast<const float4*>(s)   + row * (NEURONS / 4);
    float4* __restrict__       dst = reinterpret_cast<float4*>(out)       + row * (NEURONS / 4);

    // ---- load row, convert to monotone keys (originals recovered by decode) ----
    uint32_t key[EPT];
    #pragma unroll
    for (int i = 0; i < VPT; i++) {
        float4 v = src[tid + i * NTHREADS];
        key[4*i+0] = f2key(__float_as_uint(v.x));
        key[4*i+1] = f2key(__float_as_uint(v.y));
        key[4*i+2] = f2key(__float_as_uint(v.z));
        key[4*i+3] = f2key(__float_as_uint(v.w));
    }

    // ---- stage 1: 256-bin histogram on top byte, warp-aggregated, atomic-free ----
    #pragma unroll
    for (int w = 0; w < NWARPS; w++) whist[w][tid] = 0u;
    __syncthreads();
    {
        uint32_t* myh = whist[wid];
        #pragma unroll
        for (int e = 0; e < EPT; e++) {
            uint32_t b = key[e] >> 24;
            unsigned mk = __match_any_sync(FULL, b);
            if (lane == __ffs(mk) - 1) myh[b] += __popc(mk);  // leader-only plain RMW
            __syncwarp();                                     // visibility for next step
        }
    }
    reduce_scan_select(whist, warp_pref, KSEL, &sh_bin, &sh_krem, &sh_cnt, tid, lane, wid);
    uint32_t B    = sh_bin;
    uint32_t krem = sh_krem;
    uint32_t cnt  = sh_cnt;
    uint32_t pref = B;
    int prefShift = 24;

    // ---- compact stage-1 candidates into smem (ballot compaction, 1 atomic/warp/step) ----
    if (tid == 0) sh_ccnt = 0u;
    __syncthreads();
    #pragma unroll
    for (int e = 0; e < EPT; e++) {
        bool m = (key[e] >> 24) == B;
        unsigned bm = __ballot_sync(FULL, m);
        uint32_t base = 0;
        if (lane == 0) base = bm ? atomicAdd(&sh_ccnt, (uint32_t)__popc(bm)) : 0u;
        base = __shfl_sync(FULL, base, 0);
        if (m) cand[base + __popc(bm & lt_mask)] = key[e];
    }
    __syncthreads();
    const uint32_t c0 = sh_ccnt;   // == cnt

    // ---- refine byte-by-byte while too many survivors ----
    while (cnt > SMALL_N && prefShift > 0) {
        #pragma unroll
        for (int w = 0; w < NWARPS; w++) whist[w][tid] = 0u;
        __syncthreads();
        const int shiftB = prefShift - 8;
        const int iters = (int)((c0 + NTHREADS - 1) / NTHREADS);
        for (int it = 0; it < iters; it++) {
            int idx = tid + it * NTHREADS;
            uint32_t kv = (idx < (int)c0) ? cand[idx] : 0u;
            bool valid = (idx < (int)c0) && ((kv >> prefShift) == pref);
            uint32_t b = valid ? ((kv >> shiftB) & 0xFFu) : 0x1FFu;   // sentinel groups invalid lanes
            unsigned mk = __match_any_sync(FULL, b);
            if (valid && lane == __ffs(mk) - 1) whist[wid][b] += __popc(mk);
            __syncwarp();
        }
        reduce_scan_select(whist, warp_pref, krem, &sh_bin, &sh_krem, &sh_cnt, tid, lane, wid);
        B = sh_bin; krem = sh_krem; cnt = sh_cnt;
        pref = (pref << 8) | B;
        prefShift = shiftB;
    }

    // ---- finish: exact k-th among <=64 survivors (or fully-determined prefix) ----
    uint32_t T;
    if (cnt <= SMALL_N) {
        if (tid == 0) sh_fcnt = 0u;
        __syncthreads();
        const int iters = (int)((c0 + NTHREADS - 1) / NTHREADS);
        for (int it = 0; it < iters; it++) {
            int idx = tid + it * NTHREADS;
            uint32_t kv = (idx < (int)c0) ? cand[idx] : 0u;
            bool m = (idx < (int)c0) && ((kv >> prefShift) == pref);
            unsigned bm = __ballot_sync(FULL, m);
            uint32_t base = 0;
            if (lane == 0) base = bm ? atomicAdd(&sh_fcnt, (uint32_t)__popc(bm)) : 0u;
            base = __shfl_sync(FULL, base, 0);
            if (m) fcand[base + __popc(bm & lt_mask)] = kv;
        }
        __syncthreads();
        if (wid == 0) {
            const int n = (int)sh_fcnt;      // == cnt <= 64
            #pragma unroll
            for (int half = 0; half < 2; half++) {
                int i = lane + half * 32;
                if (i < n) {
                    uint32_t mine = fcand[i];
                    int g = 0, eq = 0;
                    for (int j = 0; j < n; j++) {
                        uint32_t o = fcand[j];
                        g  += (o > mine);
                        eq += (o == mine);
                    }
                    // k-th largest value: greater-count < krem <= greater+equal
                    if ((uint32_t)g < krem && (uint32_t)(g + eq) >= krem) sh_T = mine;
                }
            }
        }
        __syncthreads();
        T = sh_T;
    } else {
        // prefShift == 0: all survivors share the full 32-bit key
        T = pref;
    }

    // ---- apply threshold (float-domain compare matches reference `>=` exactly) ----
    const float Tf = key2f(T);
    #pragma unroll
    for (int i = 0; i < VPT; i++) {
        float x0 = key2f(key[4*i+0]);
        float x1 = key2f(key[4*i+1]);
        float x2 = key2f(key[4*i+2]);
        float x3 = key2f(key[4*i+3]);
        float4 o;
        o.x = (x0 >= Tf) ? x0 : 0.0f;
        o.y = (x1 >= Tf) ? x1 : 0.0f;
        o.z = (x2 >= Tf) ? x2 : 0.0f;
        o.w = (x3 >= Tf) ? x3 : 0.0f;
        dst[tid + i * NTHREADS] = o;
    }
}

extern "C" void kernel_launch(void* const* d_in, const int* in_sizes, int n_in,
                              void* d_out, int out_size)
{
    const float* s = (const float*)d_in[0];
    float* out = (float*)d_out;
    const int rows = out_size / NEURONS;   // 16384
    kwinners_kernel<<<rows, NTHREADS>>>(s, out);
}

// round 3
// speedup vs baseline: 1.9246x; 1.9246x over previous
#include <cuda_runtime.h>
#include <cstdint>

#define NEURONS  4096
#define KSEL     512
#define NTHREADS 256
#define VPT      4                 // float4 loads per thread (16 elems/thread)
#define NWARPS   (NTHREADS / 32)
#define SMALL_N  64

// ---- monotone float<->key transform ----
__device__ __forceinline__ uint32_t f2key(uint32_t u) {
    return u ^ (uint32_t)(((int32_t)u >> 31) | 0x80000000u);
}
__device__ __forceinline__ float key2f(uint32_t k) {
    uint32_t m = (uint32_t)((int32_t)k >> 31);
    return __uint_as_float(k ^ (0x80000000u | ~m));
}

// Reduce per-warp histograms, suffix-scan from bin 255 down, select crossing bin.
__device__ __forceinline__ void scan_select(
    uint32_t whist[NWARPS][256], uint32_t* warp_pref,
    uint32_t kk, uint32_t* sh_bin, uint32_t* sh_krem, uint32_t* sh_cnt,
    int tid, int lane, int wid)
{
    __syncthreads();
    const int bin = 255 - tid;
    uint32_t h = 0;
    #pragma unroll
    for (int w = 0; w < NWARPS; w++) h += whist[w][bin];
    uint32_t x = h;
    #pragma unroll
    for (int off = 1; off < 32; off <<= 1) {
        uint32_t y = __shfl_up_sync(0xFFFFFFFFu, x, off);
        if (lane >= off) x += y;
    }
    if (lane == 31) warp_pref[wid] = x;
    __syncthreads();
    if (wid == 0) {
        uint32_t t = (lane < NWARPS) ? warp_pref[lane] : 0u;
        #pragma unroll
        for (int off = 1; off < NWARPS; off <<= 1) {
            uint32_t y = __shfl_up_sync(0xFFFFFFFFu, t, off);
            if (lane >= off) t += y;
        }
        if (lane < NWARPS) warp_pref[lane] = t;
    }
    __syncthreads();
    uint32_t incl = x + (wid ? warp_pref[wid - 1] : 0u);
    uint32_t excl = incl - h;
    if (kk > excl && kk <= incl) {
        *sh_bin = (uint32_t)bin; *sh_krem = kk - excl; *sh_cnt = h;
    }
    __syncthreads();
}

__global__ void __launch_bounds__(NTHREADS, 6)
kwinners_kernel(const float* __restrict__ s, float* __restrict__ out)
{
    __shared__ uint32_t whist[NWARPS][256];
    __shared__ uint32_t warp_pref[NWARPS];
    __shared__ uint32_t cand[NEURONS];          // candidate keys (worst case: whole row)
    __shared__ uint32_t fcand[SMALL_N];
    __shared__ uint32_t wcnt[NWARPS][4];        // per-warp ladder counts + max key
    __shared__ uint32_t sh_bin, sh_krem, sh_cnt, sh_ccnt, sh_fcnt, sh_T;
    __shared__ uint32_t sh_rung, sh_maxk;

    const int tid  = threadIdx.x;
    const int lane = tid & 31;
    const int wid  = tid >> 5;
    const unsigned FULL = 0xFFFFFFFFu;
    const uint32_t lt_mask = (lane == 31) ? 0x7FFFFFFFu : ((1u << lane) - 1u);
    const float NEG_INF = __int_as_float(0xFF800000);

    const size_t row = blockIdx.x;
    const float4* __restrict__ src = reinterpret_cast<const float4*>(s)  + row * (NEURONS / 4);
    float4* __restrict__       dst = reinterpret_cast<float4*>(out)      + row * (NEURONS / 4);

    // ---- pass A: ladder counts + row max (cheap: compares + redux, no histogram) ----
    unsigned c0 = 0, c1 = 0, c2 = 0;
    float mx = NEG_INF;
    #pragma unroll
    for (int i = 0; i < VPT; i++) {
        float4 v = src[tid + i * NTHREADS];
        c0 += (v.x >= 1.25f) + (v.y >= 1.25f) + (v.z >= 1.25f) + (v.w >= 1.25f);
        c1 += (v.x >= 1.00f) + (v.y >= 1.00f) + (v.z >= 1.00f) + (v.w >= 1.00f);
        c2 += (v.x >= 0.75f) + (v.y >= 0.75f) + (v.z >= 0.75f) + (v.w >= 0.75f);
        mx = fmaxf(mx, fmaxf(fmaxf(v.x, v.y), fmaxf(v.z, v.w)));
    }
    c0 = __reduce_add_sync(FULL, c0);
    c1 = __reduce_add_sync(FULL, c1);
    c2 = __reduce_add_sync(FULL, c2);
    uint32_t mk = __reduce_max_sync(FULL, f2key(__float_as_uint(mx)));
    if (lane == 0) { wcnt[wid][0] = c0; wcnt[wid][1] = c1; wcnt[wid][2] = c2; wcnt[wid][3] = mk; }
    __syncthreads();
    if (tid == 0) {
        uint32_t t0 = 0, t1 = 0, t2 = 0, m = 0;
        #pragma unroll
        for (int w = 0; w < NWARPS; w++) {
            t0 += wcnt[w][0]; t1 += wcnt[w][1]; t2 += wcnt[w][2];
            m = (wcnt[w][3] > m) ? wcnt[w][3] : m;
        }
        uint32_t rung;
        if      (t0 >= KSEL) rung = 0;
        else if (t1 >= KSEL) rung = 1;
        else if (t2 >= KSEL) rung = 2;
        else                 rung = 3;
        sh_rung = rung; sh_maxk = m; sh_ccnt = 0u;
    }
    __syncthreads();
    const uint32_t rung = sh_rung;
    const uint32_t maxk = sh_maxk;
    const float Tr = (rung == 0) ? 1.25f : (rung == 1) ? 1.00f : (rung == 2) ? 0.75f : NEG_INF;

    // ---- pass B: compact candidates (x >= Tr) into smem as keys ----
    #pragma unroll
    for (int i = 0; i < VPT; i++) {
        float4 v = src[tid + i * NTHREADS];
        float xs[4] = {v.x, v.y, v.z, v.w};
        #pragma unroll
        for (int j = 0; j < 4; j++) {
            bool m = xs[j] >= Tr;
            unsigned bm = __ballot_sync(FULL, m);
            uint32_t base = 0;
            if (lane == 0 && bm) base = atomicAdd(&sh_ccnt, (uint32_t)__popc(bm));
            base = __shfl_sync(FULL, base, 0);
            if (m) cand[base + __popc(bm & lt_mask)] = f2key(__float_as_uint(xs[j]));
        }
    }
    __syncthreads();
    const uint32_t nc = sh_ccnt;                       // >= KSEL always
    const int iters = (int)((nc + NTHREADS - 1) / NTHREADS);

    // ---- range-adaptive radix refine on candidates only ----
    uint32_t lo  = (rung == 3) ? 0u : f2key(__float_as_uint(Tr));
    uint32_t hiI = maxk;                               // inclusive upper bound
    uint32_t krem = KSEL, cnt = nc;
    uint32_t T;

    for (;;) {
        if (cnt <= SMALL_N) {
            // compact survivors [lo,hiI] to fcand, exact rank-select
            if (tid == 0) sh_fcnt = 0u;
            __syncthreads();
            for (int it = 0; it < iters; it++) {
                int idx = tid + it * NTHREADS;
                uint32_t kv = (idx < (int)nc) ? cand[idx] : 0u;
                bool m = (idx < (int)nc) && kv >= lo && kv <= hiI;
                unsigned bm = __ballot_sync(FULL, m);
                uint32_t base = 0;
                if (lane == 0 && bm) base = atomicAdd(&sh_fcnt, (uint32_t)__popc(bm));
                base = __shfl_sync(FULL, base, 0);
                if (m) fcand[base + __popc(bm & lt_mask)] = kv;
            }
            __syncthreads();
            const int n = (int)sh_fcnt;                // == cnt <= 64
            if (tid < n) {
                uint32_t mine = fcand[tid];
                int g = 0, eq = 0;
                for (int j = 0; j < n; j++) {
                    uint32_t o = fcand[j];
                    g  += (o > mine);
                    eq += (o == mine);
                }
                if ((uint32_t)g < krem && (uint32_t)(g + eq) >= krem) sh_T = mine;
            }
            __syncthreads();
            T = sh_T;
            break;
        }
        if (lo == hiI) { T = lo; break; }              // all survivors share one key

        uint64_t range = (uint64_t)hiI - (uint64_t)lo + 1ull;
        int bits = 64 - __clzll((long long)(range - 1ull));
        int shf  = (bits > 8) ? (bits - 8) : 0;

        #pragma unroll
        for (int w = 0; w < NWARPS; w++) whist[w][tid] = 0u;
        __syncthreads();
        for (int it = 0; it < iters; it++) {
            int idx = tid + it * NTHREADS;
            uint32_t kv = (idx < (int)nc) ? cand[idx] : 0u;
            bool valid = (idx < (int)nc) && kv >= lo && kv <= hiI;
            uint32_t b = valid ? ((kv - lo) >> shf) : 0x1FFu;    // sentinel for invalid
            unsigned mg = __match_any_sync(FULL, b);
            if (valid && lane == (int)(__ffs(mg) - 1)) whist[wid][b] += __popc(mg);
            __syncwarp();
        }
        scan_select(whist, warp_pref, krem, &sh_bin, &sh_krem, &sh_cnt, tid, lane, wid);
        uint32_t b = sh_bin;
        krem = sh_krem; cnt = sh_cnt;
        uint32_t newlo = lo + (b << shf);
        uint64_t nh = (uint64_t)newlo + (((uint64_t)1u << shf) - 1ull);
        hiI = (uint32_t)(((uint64_t)hiI < nh) ? (uint64_t)hiI : nh);
        lo = newlo;
        if (shf == 0) { T = lo; break; }               // exact key isolated
    }

    // ---- final pass: apply threshold (float-domain `>=` matches reference) ----
    const float Tf = key2f(T);
    #pragma unroll
    for (int i = 0; i < VPT; i++) {
        float4 v = src[tid + i * NTHREADS];
        float4 o;
        o.x = (v.x >= Tf) ? v.x : 0.0f;
        o.y = (v.y >= Tf) ? v.y : 0.0f;
        o.z = (v.z >= Tf) ? v.z : 0.0f;
        o.w = (v.w >= Tf) ? v.w : 0.0f;
        dst[tid + i * NTHREADS] = o;
    }
}

extern "C" void kernel_launch(void* const* d_in, const int* in_sizes, int n_in,
                              void* d_out, int out_size)
{
    const float* s = (const float*)d_in[0];
    float* out = (float*)d_out;
    const int rows = out_size / NEURONS;   // 16384
    kwinners_kernel<<<rows, NTHREADS>>>(s, out);
}

// round 4
// speedup vs baseline: 3.6234x; 1.8827x over previous
#include <cuda_runtime.h>
#include <cstdint>

#define NEURONS  4096
#define KSEL     512
#define NTHREADS 256
#define VPT      4                 // float4 loads per thread (16 elems/thread)
#define NWARPS   (NTHREADS / 32)
#define FC_CAP   256
#define SENT     0xFFFFFFFFu

// histogram window: threshold for K/N=0.125 on N(0,1) is ~1.150 +- 0.025 (row std);
// [1.0, 1.3) is a ~6-sigma window. Anything else exercises the exact fallback.
#define H_LO     1.0f
#define H_SCALE  (256.0f / 0.3f)

// ---- monotone float<->key transform (fallback path only) ----
static __device__ __forceinline__ uint32_t f2key(uint32_t u) {
    return u ^ (uint32_t)(((int32_t)u >> 31) | 0x80000000u);
}
static __device__ __forceinline__ float key2f(uint32_t k) {
    uint32_t m = (uint32_t)((int32_t)k >> 31);
    return __uint_as_float(k ^ (0x80000000u | ~m));
}

// Block suffix-scan (descending bins) over a single 256-bin histogram; the thread
// whose bin the cumulative count crosses kk writes {bin, residual-k, bin-count}.
// Caller: hist fully written + sh_bin preset to SENT + __syncthreads() done.
static __device__ __forceinline__ void scan256(
    const uint32_t* hist, uint32_t* warp_pref,
    uint32_t base, uint32_t kk,
    uint32_t* sh_bin, uint32_t* sh_krem, uint32_t* sh_cnt,
    int tid, int lane, int wid)
{
    const int bin = 255 - tid;             // tid order == descending bins
    uint32_t h = hist[bin];
    uint32_t x = h;
    #pragma unroll
    for (int off = 1; off < 32; off <<= 1) {
        uint32_t y = __shfl_up_sync(0xFFFFFFFFu, x, off);
        if (lane >= off) x += y;
    }
    if (lane == 31) warp_pref[wid] = x;
    __syncthreads();
    if (wid == 0) {
        uint32_t t = (lane < NWARPS) ? warp_pref[lane] : 0u;
        #pragma unroll
        for (int off = 1; off < NWARPS; off <<= 1) {
            uint32_t y = __shfl_up_sync(0xFFFFFFFFu, t, off);
            if (lane >= off) t += y;
        }
        if (lane < NWARPS) warp_pref[lane] = t;
    }
    __syncthreads();
    uint32_t incl = base + x + (wid ? warp_pref[wid - 1] : 0u);
    uint32_t excl = incl - h;
    if (kk > excl && kk <= incl) {
        *sh_bin = (uint32_t)bin; *sh_krem = kk - excl; *sh_cnt = h;
    }
    __syncthreads();
}

__global__ void __launch_bounds__(NTHREADS, 6)
kwinners_kernel(const float* __restrict__ s, float* __restrict__ out)
{
    __shared__ uint32_t hist[256];
    __shared__ float    hval[256];          // one representative value per bin
    __shared__ uint32_t warp_pref[NWARPS];
    __shared__ uint32_t wabove[NWARPS];
    __shared__ float    fcand[FC_CAP];
    __shared__ uint32_t sh_bin, sh_krem, sh_cnt, sh_fcnt;
    __shared__ float    sh_T;

    const int tid  = threadIdx.x;
    const int lane = tid & 31;
    const int wid  = tid >> 5;
    const unsigned FULL = 0xFFFFFFFFu;

    const size_t row = blockIdx.x;
    const float4* __restrict__ src = reinterpret_cast<const float4*>(s)  + row * (NEURONS / 4);
    float4* __restrict__       dst = reinterpret_cast<float4*>(out)      + row * (NEURONS / 4);

    hist[tid] = 0u;
    if (tid == 0) { sh_bin = SENT; sh_fcnt = 0u; }
    __syncthreads();

    // ---- pass 1: sparse histogram in window, register count above window ----
    // Single monotone classifier: b = floor((x - H_LO) * H_SCALE).
    //   b >= 256 -> above window; 0 <= b < 256 -> histogram; b < 0 -> below (ignored)
    unsigned above = 0;
    #pragma unroll
    for (int i = 0; i < VPT; i++) {
        float4 v = src[tid + i * NTHREADS];
        float xs[4] = {v.x, v.y, v.z, v.w};
        #pragma unroll
        for (int j = 0; j < 4; j++) {
            float x = xs[j];
            int b = __float2int_rd((x - H_LO) * H_SCALE);
            above += (b >= 256);
            if ((unsigned)b < 256u) { atomicAdd(&hist[b], 1u); hval[b] = x; }
        }
    }
    above = __reduce_add_sync(FULL, above);
    if (lane == 0) wabove[wid] = above;
    __syncthreads();

    uint32_t base = 0;
    #pragma unroll
    for (int w = 0; w < NWARPS; w++) base += wabove[w];

    scan256(hist, warp_pref, base, KSEL, &sh_bin, &sh_krem, &sh_cnt, tid, lane, wid);

    float T;
    const uint32_t B = sh_bin;
    if (B != SENT && sh_cnt <= FC_CAP) {
        const uint32_t krem = sh_krem;
        const uint32_t cnt  = sh_cnt;
        if (cnt == 1u) {
            T = hval[B];                     // sole element of crossing bin
        } else {
            // collect the few bin-B elements, exact rank-select among them
            #pragma unroll
            for (int i = 0; i < VPT; i++) {
                float4 v = src[tid + i * NTHREADS];
                float xs[4] = {v.x, v.y, v.z, v.w};
                #pragma unroll
                for (int j = 0; j < 4; j++) {
                    float x = xs[j];
                    int b = __float2int_rd((x - H_LO) * H_SCALE);
                    if (b == (int)B) { uint32_t p = atomicAdd(&sh_fcnt, 1u); fcand[p] = x; }
                }
            }
            __syncthreads();
            const int n = (int)sh_fcnt;      // == cnt <= FC_CAP
            if (tid < n) {
                float mine = fcand[tid];
                int g = 0, eq = 0;
                for (int j = 0; j < n; j++) {
                    float o = fcand[j];
                    g  += (o > mine);
                    eq += (o == mine);
                }
                if ((uint32_t)g < krem && (uint32_t)(g + eq) >= krem) sh_T = mine;
            }
            __syncthreads();
            T = sh_T;
        }
    } else {
        // ---- exact 4-pass radix-select fallback (window miss / huge tie mass) ----
        uint32_t prefix = 0, kk = KSEL;
        for (int shift = 24; shift >= 0; shift -= 8) {
            hist[tid] = 0u;
            if (tid == 0) sh_bin = SENT;
            __syncthreads();
            #pragma unroll
            for (int i = 0; i < VPT; i++) {
                float4 v = src[tid + i * NTHREADS];
                float xs[4] = {v.x, v.y, v.z, v.w};
                #pragma unroll
                for (int j = 0; j < 4; j++) {
                    uint32_t key = f2key(__float_as_uint(xs[j]));
                    bool valid = (shift == 24) || ((key >> (shift + 8)) == prefix);
                    if (valid) atomicAdd(&hist[(key >> shift) & 0xFFu], 1u);
                }
            }
            __syncthreads();
            scan256(hist, warp_pref, 0u, kk, &sh_bin, &sh_krem, &sh_cnt, tid, lane, wid);
            prefix = (prefix << 8) | sh_bin;
            kk = sh_krem;
        }
        T = key2f(prefix);
    }

    // ---- apply threshold (float `>=` matches reference exactly) ----
    #pragma unroll
    for (int i = 0; i < VPT; i++) {
        float4 v = src[tid + i * NTHREADS];
        float4 o;
        o.x = (v.x >= T) ? v.x : 0.0f;
        o.y = (v.y >= T) ? v.y : 0.0f;
        o.z = (v.z >= T) ? v.z : 0.0f;
        o.w = (v.w >= T) ? v.w : 0.0f;
        dst[tid + i * NTHREADS] = o;
    }
}

extern "C" void kernel_launch(void* const* d_in, const int* in_sizes, int n_in,
                              void* d_out, int out_size)
{
    const float* s = (const float*)d_in[0];
    float* out = (float*)d_out;
    const int rows = out_size / NEURONS;   // 16384
    kwinners_kernel<<<rows, NTHREADS>>>(s, out);
}